// round 1
// baseline (speedup 1.0000x reference)
#include <cuda_runtime.h>

// ---------------- scratch (device globals; allocation-free) ----------------
__device__ float g_hA[16384*256];
__device__ float g_hB[16384*256];
__device__ float g_c [16384*256];
__device__ float g_childA[16384*256];
__device__ float g_childB[4096*256];
__device__ float g_WcatT[512*1024];     // [k][jj*4+g]  (k<256: W_ih part, else W_hh)
__device__ float g_Wcomb[256*512];      // Wt @ Wc, row-major [i][k]
__device__ float g_WcombHT[256*256];    // transposed h-half: [k][i]
__device__ float g_bcomb[256];
__device__ float g_tagE[26*256];
__device__ float g_leafout[26*256];
__device__ float g_leafxW[26*1024];     // [v][jj*4+g], biases folded in
__device__ float g_h1[256];
__device__ float g_c1[256];
__device__ float g_bzT[1024];           // [jj*4+g] = b_ih+b_hh reordered

__device__ __forceinline__ float sigm(float x){ return 1.0f/(1.0f+expf(-x)); }

// ---------------- prologue kernels ----------------
__global__ void k_init_h1c1(const float* __restrict__ W_ih, const float* __restrict__ b_ih,
                            const float* __restrict__ b_hh, const float* __restrict__ lstm_init)
{
    __shared__ float xs[256];
    __shared__ float z[1024];
    int j = threadIdx.x;
    if (j < 256) xs[j] = lstm_init[j];
    __syncthreads();
    float s = b_ih[j] + b_hh[j];
    const float* w = &W_ih[j*256];
    #pragma unroll 8
    for (int k = 0; k < 256; k++) s += xs[k]*w[k];
    z[j] = s;
    __syncthreads();
    if (j < 256){
        float c = sigm(z[j]) * tanhf(z[j+512]);     // sig(i)*tanh(g), c0=0
        g_c1[j] = c;
        g_h1[j] = sigm(z[j+768]) * tanhf(c);
    }
}

__global__ void k_build_wcatT(const float* __restrict__ W_ih, const float* __restrict__ W_hh)
{
    int idx = blockIdx.x*256 + threadIdx.x;  // 0..524287
    int k = idx >> 10, col = idx & 1023;
    int jj = col >> 2, g = col & 3;
    int row = g*256 + jj;
    g_WcatT[idx] = (k < 256) ? W_ih[row*256 + k] : W_hh[row*256 + (k-256)];
}

__global__ void k_bzT(const float* __restrict__ b_ih, const float* __restrict__ b_hh)
{
    int idx = threadIdx.x;               // 0..1023
    int jj = idx >> 2, g = idx & 3;
    g_bzT[idx] = b_ih[g*256+jj] + b_hh[g*256+jj];
}

__global__ void k_wcomb(const float* __restrict__ Wt, const float* __restrict__ Wc)
{
    int idx = blockIdx.x*256 + threadIdx.x;   // 0..131071
    int i = idx >> 9, k = idx & 511;
    float s = 0.f;
    #pragma unroll 8
    for (int j = 0; j < 256; j++) s += Wt[i*256+j]*Wc[j*512+k];
    g_Wcomb[idx] = s;
}

__global__ void k_bcomb(const float* __restrict__ Wt, const float* __restrict__ bc,
                        const float* __restrict__ bt)
{
    int i = threadIdx.x;
    float s = bt[i];
    #pragma unroll 8
    for (int j = 0; j < 256; j++) s += Wt[i*256+j]*bc[j];
    g_bcomb[i] = s;
}

__global__ void k_wcombHT()
{
    int idx = blockIdx.x*256 + threadIdx.x;   // [k][i]
    int k = idx >> 8, i = idx & 255;
    g_WcombHT[idx] = g_Wcomb[i*512 + k];
}

__global__ void k_tagE(const float* __restrict__ emb)
{
    int v = blockIdx.x, i = threadIdx.x;
    __shared__ float es[256];
    es[i] = emb[v*256 + i];
    __syncthreads();
    float s = 0.f;
    #pragma unroll 8
    for (int k = 0; k < 256; k++) s += es[k]*g_Wcomb[i*512 + 256 + k];
    g_tagE[v*256 + i] = s;
}

__global__ void k_leafout()
{
    int v = blockIdx.x, i = threadIdx.x;
    __shared__ float h1s[256];
    __shared__ float red[256];
    h1s[i] = g_h1[i];
    __syncthreads();
    float s = g_tagE[v*256+i] + g_bcomb[i];
    #pragma unroll 8
    for (int k = 0; k < 256; k++) s += h1s[k]*g_Wcomb[i*512 + k];
    red[i] = s; __syncthreads();
    for (int st = 128; st > 0; st >>= 1){ if (i < st) red[i] = fmaxf(red[i], red[i+st]); __syncthreads(); }
    float mx = red[0]; __syncthreads();
    red[i] = expf(s - mx); __syncthreads();
    for (int st = 128; st > 0; st >>= 1){ if (i < st) red[i] += red[i+st]; __syncthreads(); }
    float lse = mx + logf(red[0]);
    g_leafout[v*256 + i] = s - lse;
}

__global__ void k_leafxw(const float* __restrict__ W_ih, const float* __restrict__ b_ih,
                         const float* __restrict__ b_hh)
{
    int blk = blockIdx.x;           // 0..103 = v*4 + jb
    int v = blk >> 2, jb = blk & 3;
    int c = jb*256 + threadIdx.x;   // 0..1023 (layout [jj*4+g])
    int jj = c >> 2, g = c & 3;
    int row = g*256 + jj;
    __shared__ float lo[256];
    lo[threadIdx.x] = g_leafout[v*256 + threadIdx.x];
    __syncthreads();
    float s = b_ih[row] + b_hh[row];
    #pragma unroll 8
    for (int k = 0; k < 256; k++) s += lo[k]*W_ih[row*256 + k];
    g_leafxW[v*1024 + c] = s;
}

// ---------------- fused LSTM step: z = [x|h]@Wcat^T (+add), then cell ----------------
// MODE 0: level 7. K=256 (h only), x-contribution comes from g_leafxW gather.
// MODE 1: levels <=6. K=512, A = [x ; h].
// Block: 32 rows x 32 j-cols x 4 gates. 256 threads, acc[4][4] per thread.
template<int MODE>
__global__ void step_kernel(const float* __restrict__ hin, float* __restrict__ hout,
                            float* __restrict__ cbuf,
                            const float* __restrict__ WT,        // [k][jj*4+g]
                            const float* __restrict__ x,         // MODE1 child buf
                            const int*   __restrict__ ids,       // MODE0: idents+leafoff+t
                            const float* __restrict__ leafxW,    // MODE0
                            const float* __restrict__ bzT,       // MODE1
                            const float* __restrict__ c1,
                            int t, int first, int M)
{
    const int KD = (MODE == 0) ? 256 : 512;
    __shared__ float As[16][40];     // [kk][m], padded
    __shared__ float Ws[16][128];    // [kk][tjLocal*4+g]
    int tid = threadIdx.x;
    int tj = tid & 31;
    int tm = tid >> 5;
    int m0 = blockIdx.x * 32;
    int j0 = blockIdx.y * 32;

    float acc[4][4];
    #pragma unroll
    for (int a = 0; a < 4; a++)
        #pragma unroll
        for (int b = 0; b < 4; b++) acc[a][b] = 0.f;

    for (int k0 = 0; k0 < KD; k0 += 16){
        #pragma unroll
        for (int q = 0; q < 2; q++){
            int e = tid + q*256;
            int m = e >> 4, kk = e & 15;
            int gm = m0 + m;
            float v = 0.f;
            if (gm < M){
                int k = k0 + kk;
                if (MODE == 0){
                    v = first ? hin[k] : hin[gm*256 + k];
                } else {
                    if (k < 256) v = x[(gm*4 + t)*256 + k];
                    else         v = first ? hin[k-256] : hin[gm*256 + (k-256)];
                }
            }
            As[kk][m] = v;
        }
        #pragma unroll
        for (int q = 0; q < 2; q++){
            int e = tid + q*256;        // float4 units
            int kk = e >> 5, c4 = e & 31;
            float4 w = *reinterpret_cast<const float4*>(&WT[(k0+kk)*1024 + j0*4 + c4*4]);
            *reinterpret_cast<float4*>(&Ws[kk][c4*4]) = w;
        }
        __syncthreads();
        #pragma unroll
        for (int kk = 0; kk < 16; kk++){
            float4 b = *reinterpret_cast<const float4*>(&Ws[kk][tj*4]);
            float4 a = *reinterpret_cast<const float4*>(&As[kk][tm*4]);
            acc[0][0] = fmaf(a.x, b.x, acc[0][0]); acc[0][1] = fmaf(a.x, b.y, acc[0][1]);
            acc[0][2] = fmaf(a.x, b.z, acc[0][2]); acc[0][3] = fmaf(a.x, b.w, acc[0][3]);
            acc[1][0] = fmaf(a.y, b.x, acc[1][0]); acc[1][1] = fmaf(a.y, b.y, acc[1][1]);
            acc[1][2] = fmaf(a.y, b.z, acc[1][2]); acc[1][3] = fmaf(a.y, b.w, acc[1][3]);
            acc[2][0] = fmaf(a.z, b.x, acc[2][0]); acc[2][1] = fmaf(a.z, b.y, acc[2][1]);
            acc[2][2] = fmaf(a.z, b.z, acc[2][2]); acc[2][3] = fmaf(a.z, b.w, acc[2][3]);
            acc[3][0] = fmaf(a.w, b.x, acc[3][0]); acc[3][1] = fmaf(a.w, b.y, acc[3][1]);
            acc[3][2] = fmaf(a.w, b.z, acc[3][2]); acc[3][3] = fmaf(a.w, b.w, acc[3][3]);
        }
        __syncthreads();
    }

    int jj = j0 + tj;
    #pragma unroll
    for (int mi = 0; mi < 4; mi++){
        int gm = m0 + tm*4 + mi;
        if (gm >= M) continue;
        float zi = acc[mi][0], zf = acc[mi][1], zg = acc[mi][2], zo = acc[mi][3];
        if (MODE == 0){
            int id = ids[gm*4];
            float4 add = *reinterpret_cast<const float4*>(&leafxW[id*1024 + jj*4]);
            zi += add.x; zf += add.y; zg += add.z; zo += add.w;
        } else {
            float4 add = *reinterpret_cast<const float4*>(&bzT[jj*4]);
            zi += add.x; zf += add.y; zg += add.z; zo += add.w;
        }
        float cold = first ? c1[jj] : cbuf[gm*256 + jj];
        float cn = sigm(zf)*cold + sigm(zi)*tanhf(zg);
        cbuf[gm*256 + jj] = cn;
        hout[gm*256 + jj] = sigm(zo)*tanhf(cn);
    }
}

// ---------------- tag + log_softmax: out = logsoftmax(h@WcombH^T + tagE[id] + bcomb) --------
// Block: 16 rows x 256 cols. Threads 256: rg=tid/64 (4 rows each), cg=tid%64 (4 cols each).
__global__ void tag_kernel(const float* __restrict__ h, const int* __restrict__ ids,
                           float* __restrict__ out, int M)
{
    __shared__ float As[32][20];
    __shared__ float Ws[32][256];
    __shared__ float red[16][16];
    __shared__ float rowmax[16], rowlse[16];
    float* stag = &Ws[0][0];     // alias after GEMM phase, 16*256 floats

    int tid = threadIdx.x;
    int rg = tid >> 6;
    int cg = tid & 63;
    int m0 = blockIdx.x * 16;

    float acc[4][4];
    #pragma unroll
    for (int a = 0; a < 4; a++)
        #pragma unroll
        for (int b = 0; b < 4; b++) acc[a][b] = 0.f;

    for (int k0 = 0; k0 < 256; k0 += 32){
        #pragma unroll
        for (int q = 0; q < 2; q++){
            int e = tid + q*256;
            int m = e >> 5, kk = e & 31;
            int gm = m0 + m;
            As[kk][m] = (gm < M) ? h[gm*256 + k0 + kk] : 0.f;
        }
        #pragma unroll
        for (int q = 0; q < 8; q++){
            int e = tid + q*256;       // float4 units
            int kk = e >> 6, c4 = e & 63;
            *reinterpret_cast<float4*>(&Ws[kk][c4*4]) =
                *reinterpret_cast<const float4*>(&g_WcombHT[(k0+kk)*256 + c4*4]);
        }
        __syncthreads();
        #pragma unroll
        for (int kk = 0; kk < 32; kk++){
            float4 a = *reinterpret_cast<const float4*>(&As[kk][rg*4]);
            float4 b = *reinterpret_cast<const float4*>(&Ws[kk][cg*4]);
            acc[0][0] = fmaf(a.x, b.x, acc[0][0]); acc[0][1] = fmaf(a.x, b.y, acc[0][1]);
            acc[0][2] = fmaf(a.x, b.z, acc[0][2]); acc[0][3] = fmaf(a.x, b.w, acc[0][3]);
            acc[1][0] = fmaf(a.y, b.x, acc[1][0]); acc[1][1] = fmaf(a.y, b.y, acc[1][1]);
            acc[1][2] = fmaf(a.y, b.z, acc[1][2]); acc[1][3] = fmaf(a.y, b.w, acc[1][3]);
            acc[2][0] = fmaf(a.z, b.x, acc[2][0]); acc[2][1] = fmaf(a.z, b.y, acc[2][1]);
            acc[2][2] = fmaf(a.z, b.z, acc[2][2]); acc[2][3] = fmaf(a.z, b.w, acc[2][3]);
            acc[3][0] = fmaf(a.w, b.x, acc[3][0]); acc[3][1] = fmaf(a.w, b.y, acc[3][1]);
            acc[3][2] = fmaf(a.w, b.z, acc[3][2]); acc[3][3] = fmaf(a.w, b.w, acc[3][3]);
        }
        __syncthreads();
    }

    float4 bc = *reinterpret_cast<const float4*>(&g_bcomb[cg*4]);
    #pragma unroll
    for (int ri = 0; ri < 4; ri++){
        int r = rg*4 + ri;
        int gm = m0 + r;
        int id = (gm < M) ? ids[gm] : 0;
        float4 te = *reinterpret_cast<const float4*>(&g_tagE[id*256 + cg*4]);
        float4 v = make_float4(acc[ri][0]+te.x+bc.x, acc[ri][1]+te.y+bc.y,
                               acc[ri][2]+te.z+bc.z, acc[ri][3]+te.w+bc.w);
        *reinterpret_cast<float4*>(&stag[r*256 + cg*4]) = v;
    }
    __syncthreads();
    {
        int r = tid >> 4, s = tid & 15;
        float mx = -1e30f;
        #pragma unroll
        for (int q = 0; q < 16; q++) mx = fmaxf(mx, stag[r*256 + s*16 + q]);
        red[r][s] = mx;
    }
    __syncthreads();
    if (tid < 16){
        float mx = red[tid][0];
        #pragma unroll
        for (int s = 1; s < 16; s++) mx = fmaxf(mx, red[tid][s]);
        rowmax[tid] = mx;
    }
    __syncthreads();
    {
        int r = tid >> 4, s = tid & 15;
        float sm = 0.f, mx = rowmax[r];
        #pragma unroll
        for (int q = 0; q < 16; q++) sm += expf(stag[r*256 + s*16 + q] - mx);
        red[r][s] = sm;
    }
    __syncthreads();
    if (tid < 16){
        float sm = 0.f;
        #pragma unroll
        for (int s = 0; s < 16; s++) sm += red[tid][s];
        rowlse[tid] = logf(sm);
    }
    __syncthreads();
    #pragma unroll
    for (int q = 0; q < 16; q++){
        int e = tid + q*256;
        int r = e >> 8, i = e & 255;
        int gm = m0 + r;
        if (gm < M) out[gm*256 + i] = stag[r*256 + i] - rowmax[r] - rowlse[r];
    }
}

// ---------------- host launcher ----------------
extern "C" void kernel_launch(void* const* d_in, const int* in_sizes, int n_in,
                              void* d_out, int out_size)
{
    const int*   idents    = (const int*)  d_in[0];
    const float* emb       = (const float*)d_in[1];
    const float* W_ih      = (const float*)d_in[2];
    const float* W_hh      = (const float*)d_in[3];
    const float* b_ih      = (const float*)d_in[4];
    const float* b_hh      = (const float*)d_in[5];
    const float* Wc        = (const float*)d_in[6];
    const float* bc        = (const float*)d_in[7];
    const float* Wt        = (const float*)d_in[8];
    const float* bt        = (const float*)d_in[9];
    const float* lstm_init = (const float*)d_in[10];
    float* out = (float*)d_out;
    (void)in_sizes; (void)n_in; (void)out_size; (void)W_hh;

    void* p;
    float *hA, *hB, *cbuf, *chA, *chB, *wcatT, *leafxW, *bzT, *h1, *c1;
    cudaGetSymbolAddress(&p, g_hA);     hA     = (float*)p;
    cudaGetSymbolAddress(&p, g_hB);     hB     = (float*)p;
    cudaGetSymbolAddress(&p, g_c);      cbuf   = (float*)p;
    cudaGetSymbolAddress(&p, g_childA); chA    = (float*)p;
    cudaGetSymbolAddress(&p, g_childB); chB    = (float*)p;
    cudaGetSymbolAddress(&p, g_WcatT);  wcatT  = (float*)p;
    cudaGetSymbolAddress(&p, g_leafxW); leafxW = (float*)p;
    cudaGetSymbolAddress(&p, g_bzT);    bzT    = (float*)p;
    cudaGetSymbolAddress(&p, g_h1);     h1     = (float*)p;
    cudaGetSymbolAddress(&p, g_c1);     c1     = (float*)p;
    float* hbuf[2]  = { hA, hB };
    float* child[2] = { chA, chB };

    // prologue (tiny)
    k_init_h1c1<<<1, 1024>>>(W_ih, b_ih, b_hh, lstm_init);
    k_build_wcatT<<<2048, 256>>>(W_ih, W_hh);
    k_bzT<<<1, 1024>>>(b_ih, b_hh);
    k_wcomb<<<512, 256>>>(Wt, Wc);
    k_bcomb<<<1, 256>>>(Wt, bc, bt);
    k_wcombHT<<<256, 256>>>();
    k_tagE<<<26, 256>>>(emb);
    k_leafout<<<26, 256>>>();
    k_leafxw<<<104, 256>>>(W_ih, b_ih, b_hh);

    // level 7 (leaf children come from the 26-entry precomputed table)
    {
        int M = 16384;
        const int leaf_off = 21845;   // (4^8-1)/3
        const int off7 = 5461;        // (4^7-1)/3
        for (int t = 0; t < 4; t++){
            dim3 grid((M + 31)/32, 8);
            const float* hin = (t == 0) ? h1 : hbuf[(t+1)&1];
            step_kernel<0><<<grid, 256>>>(hin, hbuf[t&1], cbuf,
                                          wcatT + 256*1024,   // W_hh^T portion
                                          nullptr, idents + leaf_off + t,
                                          leafxW, nullptr, c1, t, (t==0)?1:0, M);
        }
        tag_kernel<<<(M + 15)/16, 256>>>(hbuf[1], idents + off7, child[0], M);
    }

    // levels 6..0
    int cur = 0;  // child[cur] holds child_out of level l+1
    for (int l = 6; l >= 0; l--){
        int M = 1 << (2*l);
        int off = (M - 1)/3;
        for (int t = 0; t < 4; t++){
            dim3 grid((M + 31)/32, 8);
            const float* hin = (t == 0) ? h1 : hbuf[(t+1)&1];
            step_kernel<1><<<grid, 256>>>(hin, hbuf[t&1], cbuf,
                                          wcatT, child[cur], nullptr,
                                          nullptr, bzT, c1, t, (t==0)?1:0, M);
        }
        float* o = (l == 0) ? out : child[cur ^ 1];
        tag_kernel<<<(M + 15)/16, 256>>>(hbuf[1], idents + off, o, M);
        cur ^= 1;
    }
}